// round 17
// baseline (speedup 1.0000x reference)
#include <cuda_runtime.h>
#include <cuda_bf16.h>
#include <cuda_fp16.h>
#include <cstdint>
#include <cstddef>

#define MROWS 8192
#define DIN   4096
#define DOUT  4096
#define RNK   16
#define LDKX  4160
#define TN    256
#define TK    64
#define NKC   65
#define NST   3
#define NTILES 512          // (8192/256) * (4096/256)
#define GRID_G 148
#define THREADS_G 288       // 8 epilogue warps + 1 producer warp
#define SCALING_F 2.0f

#if defined(__CUDA_ARCH__) && (defined(__CUDA_ARCH_FEAT_SM103_ALL) || \
    defined(__CUDA_ARCH_FEAT_SM100_ALL) || defined(__CUDA_ARCH_SPECIFIC__) || \
    defined(__CUDA_ARCH_FAMILY_SPECIFIC__))
#define TC5 1
#else
#define TC5 0
#endif

// Pre-swizzled tiled fp16 layouts (byte image == SMEM image), 32KB/256-row blocks:
//   g_xf: [mt=32][kc=65] blocks of 32768B (256 rows x 128B, SW128-permuted)
//   g_wf: [nt=16][kc=65] blocks of 32768B
__device__ __align__(128) __half g_xf[(size_t)MROWS * LDKX];
__device__ __align__(128) __half g_wf[(size_t)DOUT * LDKX];
__device__ __align__(128) float  g_xa[MROWS * RNK];

#define SWZ128(o) ((o) ^ (((o) >> 3) & 0x70))

__device__ __forceinline__ uint32_t smem_u32(const void* p) {
    uint32_t a;
    asm("{ .reg .u64 t; cvta.to.shared.u64 t, %1; cvt.u32.u64 %0, t; }" : "=r"(a) : "l"(p));
    return a;
}

#if TC5
__device__ __forceinline__ uint32_t elect_one() {
    uint32_t p;
    asm volatile("{\n\t.reg .pred p;\n\telect.sync _|p, 0xFFFFFFFF;\n\tselp.b32 %0, 1, 0, p;\n\t}" : "=r"(p));
    return p;
}
__device__ __forceinline__ void bulkcp(uint32_t dst, const void* src, uint32_t bytes, uint32_t mbar) {
    asm volatile(
        "cp.async.bulk.shared::cta.global.mbarrier::complete_tx::bytes [%0], [%1], %2, [%3];"
        :: "r"(dst), "l"(src), "r"(bytes), "r"(mbar) : "memory");
}
__device__ __forceinline__ void mbar_expect(uint32_t mbar, uint32_t bytes) {
    asm volatile("mbarrier.arrive.expect_tx.shared.b64 _, [%0], %1;"
                 :: "r"(mbar), "r"(bytes) : "memory");
}
__device__ __forceinline__ void mbar_wait(uint32_t mbar, uint32_t parity) {
    asm volatile(
        "{\n\t.reg .pred P;\n\t"
        "W_%=:\n\t"
        "mbarrier.try_wait.parity.acquire.cta.shared::cta.b64 P, [%0], %1, 0x989680;\n\t"
        "@P bra.uni D_%=;\n\t"
        "bra.uni W_%=;\n\t"
        "D_%=:\n\t}"
        :: "r"(mbar), "r"(parity) : "memory");
}
__device__ __forceinline__ uint64_t make_desc(uint32_t addr) {   // SW128 K-major
    const uint64_t base =
        (uint64_t(2) << 61) | (uint64_t(1) << 46) | (uint64_t(64) << 32) | (uint64_t(1) << 16);
    return base | ((uint64_t)(addr >> 4) & 0x3FFFULL);
}
// cg1: fp16 in, fp32 acc, M=128 per accumulator, N=256
#define MMA_IDESC ((1u << 4) | ((TN / 8) << 17) | ((128 / 16) << 24))

__device__ __forceinline__ void mma_ss(uint32_t d, uint64_t da, uint64_t db, uint32_t acc) {
    asm volatile(
        "{\n\t.reg .pred p;\n\t"
        "setp.ne.u32 p, %5, 0;\n\t"
        "tcgen05.mma.cta_group::1.kind::f16 [%0], %1, %2, %3, {%4, %4, %4, %4}, p;\n\t}"
        :: "r"(d), "l"(da), "l"(db), "r"(MMA_IDESC), "r"(0u), "r"(acc) : "memory");
}
__device__ __forceinline__ void ldtm32(uint32_t a, uint32_t* r) {
    asm volatile(
        "tcgen05.ld.sync.aligned.32x32b.x32.b32 "
        "{%0,%1,%2,%3,%4,%5,%6,%7,%8,%9,%10,%11,%12,%13,%14,%15,"
        "%16,%17,%18,%19,%20,%21,%22,%23,%24,%25,%26,%27,%28,%29,%30,%31}, [%32];"
        : "=r"(r[0]), "=r"(r[1]), "=r"(r[2]), "=r"(r[3]), "=r"(r[4]), "=r"(r[5]), "=r"(r[6]), "=r"(r[7]),
          "=r"(r[8]), "=r"(r[9]), "=r"(r[10]), "=r"(r[11]), "=r"(r[12]), "=r"(r[13]), "=r"(r[14]), "=r"(r[15]),
          "=r"(r[16]), "=r"(r[17]), "=r"(r[18]), "=r"(r[19]), "=r"(r[20]), "=r"(r[21]), "=r"(r[22]), "=r"(r[23]),
          "=r"(r[24]), "=r"(r[25]), "=r"(r[26]), "=r"(r[27]), "=r"(r[28]), "=r"(r[29]), "=r"(r[30]), "=r"(r[31])
        : "r"(a));
    asm volatile("tcgen05.wait::ld.sync.aligned;" ::: "memory");
}
#define BAR_ACC() asm volatile("bar.sync 1, %0;" :: "n"(THREADS_G) : "memory")
#define BAR_EPI() asm volatile("bar.sync 2, %0;" :: "n"(THREADS_G) : "memory")
#endif  // TC5

// ---- kernel 1 (fused): xa = x @ A^T  AND  x -> fp16 pre-swizzled tiles ----
__global__ __launch_bounds__(256) void k_xa(const float* __restrict__ x,
                                            const float* __restrict__ A) {
    __shared__ float sA[16 * 512];
    const int tid = threadIdx.x, wid = tid >> 5, lid = tid & 31;
    const int m = blockIdx.x * 8 + wid;
    float acc[RNK];
#pragma unroll
    for (int r = 0; r < RNK; r++) acc[r] = 0.f;
    for (int k0 = 0; k0 < DIN; k0 += 512) {
        __syncthreads();
        for (int i = tid; i < 2048; i += 256) {
            int r = i >> 7, k4 = i & 127;
            ((float4*)sA)[i] = *(const float4*)(A + (size_t)r * DIN + k0 + k4 * 4);
        }
        __syncthreads();
        const float4* xr = (const float4*)(x + (size_t)m * DIN + k0);
#pragma unroll
        for (int j = 0; j < 4; j++) {
            const int k4 = lid + 32 * j;
            const float4 xv = xr[k4];
            // fused fp16 store to pre-swizzled tiled layout
            {
                const int c0 = k0 + k4 * 4;
                __half2 h0 = __floats2half2_rn(xv.x, xv.y);
                __half2 h1 = __floats2half2_rn(xv.z, xv.w);
                const size_t blk = ((size_t)(m >> 8) * NKC + (c0 >> 6)) * 32768u;
                const uint32_t off =
                    SWZ128((uint32_t)(((m & 255) << 7) + (((c0 >> 3) & 7) << 4))) + ((c0 & 4) << 1);
                *(uint2*)((char*)g_xf + blk + off) =
                    make_uint2(*(uint32_t*)&h0, *(uint32_t*)&h1);
            }
#pragma unroll
            for (int r = 0; r < RNK; r++) {
                float4 av = ((const float4*)sA)[r * 128 + k4];
                acc[r] = fmaf(xv.x, av.x, acc[r]);
                acc[r] = fmaf(xv.y, av.y, acc[r]);
                acc[r] = fmaf(xv.z, av.z, acc[r]);
                acc[r] = fmaf(xv.w, av.w, acc[r]);
            }
        }
    }
#pragma unroll
    for (int r = 0; r < RNK; r++) {
        float v = acc[r];
        v += __shfl_xor_sync(0xffffffffu, v, 16);
        v += __shfl_xor_sync(0xffffffffu, v, 8);
        v += __shfl_xor_sync(0xffffffffu, v, 4);
        v += __shfl_xor_sync(0xffffffffu, v, 2);
        v += __shfl_xor_sync(0xffffffffu, v, 1);
        if (lid == 0) g_xa[m * RNK + r] = v;
    }
}

// ---- fp16 convert helpers ----
__device__ __forceinline__ void cvt8(const float* v, void* dst) {
    uint32_t w[4];
#pragma unroll
    for (int k = 0; k < 4; k++) {
        __half2 h2 = __floats2half2_rn(v[2 * k], v[2 * k + 1]);
        w[k] = *(uint32_t*)&h2;
    }
    *(uint4*)dst = make_uint4(w[0], w[1], w[2], w[3]);
}
__global__ __launch_bounds__(256) void k_conv_w_main(const float* __restrict__ W) {
    const int n = blockIdx.y;
    const int c0 = (blockIdx.x * 256 + threadIdx.x) * 8;
    float v[8];
    *(float4*)v       = *(const float4*)(W + (size_t)n * DIN + c0);
    *(float4*)(v + 4) = *(const float4*)(W + (size_t)n * DIN + c0 + 4);
    const size_t blk = ((size_t)(n >> 8) * NKC + (c0 >> 6)) * 32768u;
    const uint32_t sw = SWZ128((uint32_t)(((n & 255) << 7) + (((c0 >> 3) & 7) << 4)));
    cvt8(v, (char*)g_wf + blk + sw);
}
__global__ __launch_bounds__(256) void k_edge_x() {
    const int idx = blockIdx.x * 256 + threadIdx.x;
    const int row = idx >> 3, seg = idx & 7;
    float v[8];
#pragma unroll
    for (int j = 0; j < 8; j++) {
        const int c = seg * 8 + j;
        v[j] = (c < RNK) ? SCALING_F * g_xa[row * RNK + c] : 0.f;
    }
    const size_t blk = ((size_t)(row >> 8) * NKC + 64) * 32768u;
    const uint32_t sw = SWZ128((uint32_t)(((row & 255) << 7) + (seg << 4)));
    cvt8(v, (char*)g_xf + blk + sw);
}
__global__ __launch_bounds__(256) void k_edge_w(const float* __restrict__ lB) {
    const int idx = blockIdx.x * 256 + threadIdx.x;
    const int row = idx >> 3, seg = idx & 7;
    float v[8];
#pragma unroll
    for (int j = 0; j < 8; j++) {
        const int c = seg * 8 + j;
        v[j] = (c < RNK) ? lB[row * RNK + c] : 0.f;
    }
    const size_t blk = ((size_t)(row >> 8) * NKC + 64) * 32768u;
    const uint32_t sw = SWZ128((uint32_t)(((row & 255) << 7) + (seg << 4)));
    cvt8(v, (char*)g_wf + blk + sw);
}

// ---- main GEMM: persistent, cg1 fp16 256x256 tiles, producer warp + 8 epilogue warps ----
// SMEM: [0] tmem ptr; full[3]@16..32; done[3]@48..64; stages@2048 (3 x 65536)
#define SMEM_STAGE0 2048
#define STAGE_BYTES 65536
#define OFF_A 0
#define OFF_B 32768
#define SMEM_TOTAL (SMEM_STAGE0 + NST * STAGE_BYTES)

__global__ __launch_bounds__(THREADS_G, 1)
void k_gemm(const float* __restrict__ bias, float* __restrict__ out,
            const float* __restrict__ x, const float* __restrict__ W,
            const float* __restrict__ lB) {
    extern __shared__ char smem[];
    const int tid = threadIdx.x;
    const int wid = tid >> 5, lid = tid & 31;
    int tl[4];
    int T = 0;
    for (int t = blockIdx.x; t < NTILES; t += GRID_G) tl[T++] = t;
#if TC5
    const uint32_t sbase = smem_u32(smem);
    const uint32_t FUL = sbase + 16, DON = sbase + 48;

    if (wid == 0) {
        asm volatile("tcgen05.alloc.cta_group::1.sync.aligned.shared::cta.b32 [%0], %1;"
                     :: "r"(sbase), "r"(512u) : "memory");
        asm volatile("tcgen05.relinquish_alloc_permit.cta_group::1.sync.aligned;");
    }
    if (tid < NST)
        asm volatile("mbarrier.init.shared.b64 [%0], 1;" :: "r"(FUL + tid * 8) : "memory");
    else if (tid < 2 * NST)
        asm volatile("mbarrier.init.shared.b64 [%0], 1;" :: "r"(DON + (tid - NST) * 8) : "memory");
    __syncthreads();
    uint32_t tmem;
    asm volatile("ld.shared.b32 %0, [%1];" : "=r"(tmem) : "r"(sbase));

    const int total = T * NKC;

    if (wid == 8) {
        // ---------- producer warp (all lanes converged; elected lane issues asm) ----------
        const uint32_t el = elect_one();
        auto load_chunk = [&](int j) {
            const int tile = tl[j / NKC];
            const int kt = j - (j / NKC) * NKC;
            const int sl = j % NST;
            if (el) {
                const char* asrc = (char*)g_xf + ((size_t)(tile >> 4) * NKC + kt) * 32768u;
                const char* bsrc = (char*)g_wf + ((size_t)(tile & 15) * NKC + kt) * 32768u;
                const uint32_t st = sbase + SMEM_STAGE0 + sl * STAGE_BYTES;
                const uint32_t fm = FUL + sl * 8;
                mbar_expect(fm, STAGE_BYTES);
                bulkcp(st + OFF_A, asrc, 32768u, fm);
                bulkcp(st + OFF_B, bsrc, 32768u, fm);
            }
        };
        load_chunk(0);
        load_chunk(1);
#pragma unroll 1
        for (int ti = 0; ti < T; ti++) {
            if (ti > 0) {
                BAR_EPI();   // previous tile's epilogue finished reading TMEM
                asm volatile("tcgen05.fence::after_thread_sync;" ::: "memory");
            }
#pragma unroll 1
            for (int kt = 0; kt < NKC; kt++) {
                const int j = ti * NKC + kt;
                if (j + 2 < total) {
                    if (j >= 1)
                        mbar_wait(DON + ((j - 1) % NST) * 8, (uint32_t)(((j - 1) / NST) & 1));
                    load_chunk(j + 2);
                }
                mbar_wait(FUL + (j % NST) * 8, (uint32_t)((j / NST) & 1));
                if (el) {
                    const uint32_t st = sbase + SMEM_STAGE0 + (j % NST) * STAGE_BYTES;
                    const uint64_t dA = make_desc(st + OFF_A);
                    const uint64_t dB = make_desc(st + OFF_B);
#pragma unroll
                    for (int h = 0; h < 2; h++) {
                        const uint32_t d = tmem + h * 256;
                        const uint64_t ao = (uint64_t)(h * 1024);   // 128 rows * 128B / 16
#pragma unroll
                        for (int ks = 0; ks < 4; ks++)
                            mma_ss(d, dA + ao + 2 * ks, dB + 2 * ks,
                                   (kt == 0 && ks == 0) ? 0u : 1u);
                    }
                    asm volatile(
                        "tcgen05.commit.cta_group::1.mbarrier::arrive::one.shared::cluster.b64 [%0];"
                        :: "r"(DON + (j % NST) * 8) : "memory");
                }
            }
            {   // accumulator complete for this tile (re-waiting same parity later is a no-op)
                const int jl = ti * NKC + NKC - 1;
                mbar_wait(DON + (jl % NST) * 8, (uint32_t)((jl / NST) & 1));
            }
            BAR_ACC();   // release epilogue for this tile
        }
        BAR_EPI();       // match epilogue's final arrive
    } else {
        // ---------- 8 epilogue warps ----------
#pragma unroll 1
        for (int ti = 0; ti < T; ti++) {
            BAR_ACC();
            asm volatile("tcgen05.fence::after_thread_sync;" ::: "memory");
            const int tile = tl[ti];
            const int m0 = (tile >> 4) * 256, n0 = (tile & 15) * 256;
            const int half = wid >> 2, rw = wid & 3;
            const uint32_t acc_base = tmem + half * 256;
            const float* bs = bias + n0;
            float* orow = out + (size_t)(m0 + half * 128 + rw * 32 + lid) * DOUT + n0;
#pragma unroll 1
            for (int c0 = 0; c0 < TN; c0 += 32) {
                uint32_t r[32];
                ldtm32(acc_base + c0, r);
#pragma unroll
                for (int j = 0; j < 32; j += 4) {
                    float4 v;
                    v.x = __uint_as_float(r[j + 0]) + __ldg(bs + c0 + j + 0);
                    v.y = __uint_as_float(r[j + 1]) + __ldg(bs + c0 + j + 1);
                    v.z = __uint_as_float(r[j + 2]) + __ldg(bs + c0 + j + 2);
                    v.w = __uint_as_float(r[j + 3]) + __ldg(bs + c0 + j + 3);
                    *(float4*)(orow + c0 + j) = v;
                }
            }
            asm volatile("tcgen05.fence::before_thread_sync;" ::: "memory");
            BAR_EPI();   // TMEM free for next tile's MMAs
        }
    }
    __syncthreads();
    if (wid == 0)
        asm volatile("tcgen05.dealloc.cta_group::1.sync.aligned.b32 %0, %1;"
                     :: "r"(tmem), "r"(512u));
#else
    // ---------- fp32 SIMT fallback (base sm_103 target; persistent tiles) ----------
    float* As = (float*)smem;            // [128][17]
    float* Bs = As + 128 * 17;           // [128][17]
    const int tx = tid & 15, ty = tid >> 4;   // ty up to 17; guard ty<16 for compute
#pragma unroll 1
    for (int ti = 0; ti < T; ti++) {
        const int tile = tl[ti];
        const int m0 = (tile >> 4) * 256, n0 = (tile & 15) * 256;
#pragma unroll 1
        for (int mh = 0; mh < 2; mh++) {
            const int mb = m0 + mh * 128;
#pragma unroll 1
            for (int nh = 0; nh < 2; nh++) {
                const int nb = n0 + nh * 128;
                float acc[8][8];
#pragma unroll
                for (int i = 0; i < 8; i++)
#pragma unroll
                    for (int j = 0; j < 8; j++) acc[i][j] = 0.f;
#pragma unroll 1
                for (int k0 = 0; k0 < DIN; k0 += 16) {
                    __syncthreads();
                    for (int i = tid; i < 128 * 16; i += THREADS_G) {
                        const int m = i >> 4, kk = i & 15;
                        As[m * 17 + kk] = x[(size_t)(mb + m) * DIN + k0 + kk];
                        Bs[m * 17 + kk] = W[(size_t)(nb + m) * DIN + k0 + kk];
                    }
                    __syncthreads();
                    if (ty < 16) {
#pragma unroll
                        for (int kk = 0; kk < 16; kk++) {
                            float ra[8], rb[8];
#pragma unroll
                            for (int j = 0; j < 8; j++) {
                                ra[j] = As[(ty * 8 + j) * 17 + kk];
                                rb[j] = Bs[(tx * 8 + j) * 17 + kk];
                            }
#pragma unroll
                            for (int i = 0; i < 8; i++)
#pragma unroll
                                for (int j = 0; j < 8; j++)
                                    acc[i][j] = fmaf(ra[i], rb[j], acc[i][j]);
                        }
                    }
                }
                if (ty < 16) {
#pragma unroll
                    for (int i = 0; i < 8; i++) {
                        const int m = mb + ty * 8 + i;
                        const float* xar = g_xa + m * RNK;
#pragma unroll
                        for (int j = 0; j < 8; j++) {
                            const int n = nb + tx * 8 + j;
                            float l = 0.f;
#pragma unroll
                            for (int r = 0; r < RNK; r++) l = fmaf(xar[r], lB[n * RNK + r], l);
                            out[(size_t)m * DOUT + n] = acc[i][j] + bias[n] + SCALING_F * l;
                        }
                    }
                }
                __syncthreads();
            }
        }
    }
#endif
}

extern "C" void kernel_launch(void* const* d_in, const int* in_sizes, int n_in,
                              void* d_out, int out_size) {
    const float* x  = (const float*)d_in[0];
    const float* W  = (const float*)d_in[1];
    const float* b  = (const float*)d_in[2];
    const float* lA = (const float*)d_in[3];
    const float* lB = (const float*)d_in[4];
    float* out = (float*)d_out;

    cudaFuncSetAttribute(k_gemm, cudaFuncAttributeMaxDynamicSharedMemorySize, SMEM_TOTAL);

    k_xa<<<MROWS / 8, 256>>>(x, lA);                       // fused: xa + x->fp16 tiles
    k_conv_w_main<<<dim3(DIN / 2048, DOUT), 256>>>(W);
    k_edge_x<<<MROWS * 8 / 256, 256>>>();
    k_edge_w<<<DOUT * 8 / 256, 256>>>(lB);
    k_gemm<<<GRID_G, THREADS_G, SMEM_TOTAL>>>(b, out, x, W, lB);
}